// round 6
// baseline (speedup 1.0000x reference)
#include <cuda_runtime.h>
#include <cuda_fp16.h>

#define D     128
#define ROWS  128
#define TPB   256
#define SPT   132            // sPiT row stride (padded, %4==0 for float4)
#define SVS   129            // sV   row stride (odd: spreads column-store banks)

// shared memory layout (floats)
#define OFF_PIT 0            // sPiT[k*SPT + j]   (reused as sV[j*SVS + r] after GEMM1)
#define OFF_PI  16896        // sPi [j*D   + k]
#define OFF_X   33280        // sX  [k*D   + r]   (x * invnorm, transposed)
#define OFF_NQ  49664        // sNq [r]
#define SMEM_FLOATS 49792    // 199,168 bytes

typedef unsigned long long ull;

union F4U { float4 f4; ull u[2]; float s[4]; };

__device__ __forceinline__ ull dup2(float v) {
    ull r; unsigned u = __float_as_uint(v);
    asm("mov.b64 %0, {%1, %1};" : "=l"(r) : "r"(u));
    return r;
}
__device__ __forceinline__ void ffma2(ull& d, ull a, ull b) {
    asm("fma.rn.f32x2 %0, %1, %2, %3;" : "=l"(d) : "l"(a), "l"(b), "l"(d));
}
__device__ __forceinline__ void fmul2(ull& d, ull a, ull b) {
    asm("mul.rn.f32x2 %0, %1, %2;" : "=l"(d) : "l"(a), "l"(b));
}
__device__ __forceinline__ void unpack2(ull v, float& a, float& b) {
    unsigned ua, ub;
    asm("mov.b64 {%0, %1}, %2;" : "=r"(ua), "=r"(ub) : "l"(v));
    a = __uint_as_float(ua); b = __uint_as_float(ub);
}

__global__ void __launch_bounds__(TPB, 1)
tq_kernel(const float* __restrict__ x, const float* __restrict__ Pi,
          const float* __restrict__ cen, const float* __restrict__ bnd,
          float* __restrict__ out)
{
    extern __shared__ float sm[];
    float* sPiT = sm + OFF_PIT;
    float* sV   = sm + OFF_PIT;   // overlays sPiT (dead after GEMM1)
    float* sPi  = sm + OFF_PI;
    float* sX   = sm + OFF_X;
    float* sNq  = sm + OFF_NQ;

    const int tid = threadIdx.x;

    // ---- codebook -> registers: interior boundaries + centroid deltas ----
    float B[15], Dl[15];
    const float c0 = cen[0];
    {
        float prev = c0;
#pragma unroll
        for (int i = 0; i < 15; i++) {
            B[i]  = bnd[i + 1];
            float c = cen[i + 1];
            Dl[i] = c - prev;
            prev  = c;
        }
    }

    // ---- load Pi: row-major copy + padded transpose ----
#pragma unroll
    for (int i = 0; i < 16; i++) {
        int idx = tid + i * TPB;                 // float4 index over 4096
        ((float4*)sPi)[idx] = ((const float4*)Pi)[idx];
    }
#pragma unroll
    for (int i = 0; i < 64; i++) {
        int idx = tid + i * TPB;                 // scalar index over 16384
        int j = idx >> 7, k = idx & 127;
        sPiT[k * SPT + j] = Pi[idx];
    }

    // ---- load x tile, compute norms, store x*invn transposed [k][r] ----
    {
        const int r = tid >> 1, h = tid & 1;
        const float4* xr = (const float4*)(x + ((size_t)blockIdx.x * ROWS + r) * D + h * 64);
        float4 xv[16];
        float ss = 0.f;
#pragma unroll
        for (int i = 0; i < 16; i++) {
            xv[i] = xr[i];
            ss += xv[i].x * xv[i].x + xv[i].y * xv[i].y
                + xv[i].z * xv[i].z + xv[i].w * xv[i].w;
        }
        ss += __shfl_xor_sync(0xffffffffu, ss, 1);
        float norm = sqrtf(ss);
        float invn = 1.0f / (norm + 1e-8f);
        if (h == 0) sNq[r] = __half2float(__float2half(norm));  // fp16 round trip
#pragma unroll
        for (int i = 0; i < 16; i++) {
            int k0 = h * 64 + i * 4;
            sX[(k0    ) * D + r] = xv[i].x * invn;
            sX[(k0 + 1) * D + r] = xv[i].y * invn;
            sX[(k0 + 2) * D + r] = xv[i].z * invn;
            sX[(k0 + 3) * D + r] = xv[i].w * invn;
        }
    }
    __syncthreads();

    // 8x8 per-thread tile:
    //   rows: {r0..r0+3} U {64+r0..64+r0+3},  r0 = 4*(tid>>4)
    //   cols: {c0..c0+3} U {64+c0..64+c0+3},  c0 = 4*(tid&15)
    const int tx  = tid & 15;
    const int ty  = tid >> 4;
    const int r0  = ty * 4;
    const int c0_ = tx * 4;

    // acc[p][q]: p = row index (0-3 lower half, 4-7 upper), q = col-pair
    //   q=0: cols c0,c0+1   q=1: cols c0+2,c0+3
    //   q=2: cols 64+c0,64+c0+1   q=3: cols 64+c0+2,64+c0+3
    ull acc[8][4];
#pragma unroll
    for (int p = 0; p < 8; p++)
#pragma unroll
        for (int q = 0; q < 4; q++) acc[p][q] = 0ull;

    // ---- GEMM1: rotated[r][j] = sum_k sX[k][r] * PiT[k][j] ----
#pragma unroll 4
    for (int k = 0; k < D; k++) {
        const float* xk = sX + k * D;
        F4U a0, a1;
        a0.f4 = *(const float4*)(xk + r0);        // 16B aligned (r0 % 4 == 0, D % 4 == 0)
        a1.f4 = *(const float4*)(xk + 64 + r0);
        const float* pk = sPiT + k * SPT;          // SPT % 4 == 0
        F4U b0, b1;
        b0.f4 = *(const float4*)(pk + c0_);
        b1.f4 = *(const float4*)(pk + 64 + c0_);
        ull ad[8];
#pragma unroll
        for (int p = 0; p < 4; p++) { ad[p] = dup2(a0.s[p]); ad[p + 4] = dup2(a1.s[p]); }
#pragma unroll
        for (int p = 0; p < 8; p++) {
            ffma2(acc[p][0], ad[p], b0.u[0]);
            ffma2(acc[p][1], ad[p], b0.u[1]);
            ffma2(acc[p][2], ad[p], b1.u[0]);
            ffma2(acc[p][3], ad[p], b1.u[1]);
        }
    }
    __syncthreads();   // all reads of sPiT / sX complete before sV overwrite

    // ---- quantize (Lloyd-Max bucketize, side='left') & store sV[j][r] ----
#pragma unroll
    for (int p = 0; p < 8; p++) {
        const int r = r0 + (p & 3) + (p >> 2) * 64;
#pragma unroll
        for (int q = 0; q < 4; q++) {
            const int j0 = c0_ + (q & 1) * 2 + (q >> 1) * 64;
            float v0, v1;
            unpack2(acc[p][q], v0, v1);
            float w0 = c0, w1 = c0;
#pragma unroll
            for (int i = 0; i < 15; i++) {
                if (v0 > B[i]) w0 += Dl[i];
                if (v1 > B[i]) w1 += Dl[i];
            }
            sV[(j0    ) * SVS + r] = w0;
            sV[(j0 + 1) * SVS + r] = w1;
        }
    }
    __syncthreads();

    // ---- GEMM2: recon[r][k] = sum_j sV[j][r] * Pi[j][k] ----
#pragma unroll
    for (int p = 0; p < 8; p++)
#pragma unroll
        for (int q = 0; q < 4; q++) acc[p][q] = 0ull;

#pragma unroll 4
    for (int j = 0; j < D; j++) {
        const float* vj = sV + j * SVS;            // SVS odd -> SCALAR loads only
        const float* pj = sPi + j * D;
        F4U b0, b1;
        b0.f4 = *(const float4*)(pj + c0_);
        b1.f4 = *(const float4*)(pj + 64 + c0_);
        ull ad[8];
#pragma unroll
        for (int p = 0; p < 4; p++) {
            ad[p]     = dup2(vj[r0 + p]);          // broadcast LDS.32
            ad[p + 4] = dup2(vj[64 + r0 + p]);
        }
#pragma unroll
        for (int p = 0; p < 8; p++) {
            ffma2(acc[p][0], ad[p], b0.u[0]);
            ffma2(acc[p][1], ad[p], b0.u[1]);
            ffma2(acc[p][2], ad[p], b1.u[0]);
            ffma2(acc[p][3], ad[p], b1.u[1]);
        }
    }

    // ---- epilogue: scale by fp16-roundtripped norm, vectorized store ----
    const size_t obase = (size_t)blockIdx.x * ROWS * D;
#pragma unroll
    for (int p = 0; p < 8; p++) {
        const int r = r0 + (p & 3) + (p >> 2) * 64;
        ull nd = dup2(sNq[r]);
#pragma unroll
        for (int q = 0; q < 4; q++) fmul2(acc[p][q], acc[p][q], nd);
        F4U o0, o1;
        o0.u[0] = acc[p][0]; o0.u[1] = acc[p][1];
        o1.u[0] = acc[p][2]; o1.u[1] = acc[p][3];
        float* orow = out + obase + (size_t)r * D;
        *(float4*)(orow + c0_)      = o0.f4;
        *(float4*)(orow + 64 + c0_) = o1.f4;
    }
}

extern "C" void kernel_launch(void* const* d_in, const int* in_sizes, int n_in,
                              void* d_out, int out_size)
{
    const float* x   = (const float*)d_in[0];
    const float* Pi  = (const float*)d_in[1];
    const float* cen = (const float*)d_in[2];
    const float* bnd = (const float*)d_in[3];
    float* out = (float*)d_out;

    const int n_rows = in_sizes[0] / D;        // 262144
    const int blocks = n_rows / ROWS;          // 2048

    const size_t smem = SMEM_FLOATS * sizeof(float);
    cudaFuncSetAttribute(tq_kernel, cudaFuncAttributeMaxDynamicSharedMemorySize, (int)smem);
    tq_kernel<<<blocks, TPB, smem>>>(x, Pi, cen, bnd, out);
}